// round 13
// baseline (speedup 1.0000x reference)
#include <cuda_runtime.h>
#include <cuda_bf16.h>
#include <cstdint>

#define NROWS 8192
#define DIM   128
#define CHUNK 128                  // samples per tile
#define NBLOCKS 128                // b<64: X chunk b (+diag); b>=64: Y chunk b-64
#define NTHREADS 512               // 16 warps
#define NPART 64                   // partials per matrix
#define FIN_BLOCKS 64

// ---------------- device-global scratch (no allocations allowed) -----------
// g_part[m][i] = block i's raw partial of P_m = H^T H + 2 H^T L (8 MB total).
// Fully overwritten every launch -> no zeroing pass needed.
__device__ float    g_part[2][NPART][DIM * DIM];
__device__ float    g_S1;               // <Px,Py>_F accumulator
__device__ float    g_S2;               // sum d_i^2
__device__ float    g_S3;               // sum d_i
__device__ unsigned g_ticket;

// ---------------- helpers ---------------------------------------------------
__device__ __forceinline__ uint32_t smem_u32(const void* p) {
    uint32_t a;
    asm("{ .reg .u64 t; cvta.to.shared.u64 t, %1; cvt.u32.u64 %0, t; }" : "=r"(a) : "l"(p));
    return a;
}

// Tile stored SAMPLE-major: S[k][d]; two 16KB subtiles by d>>6; SW128 swizzle.
__device__ __forceinline__ uint32_t toff(int k, int d) {
    uint32_t o = (uint32_t)(k * 128 + (d & 63) * 2);
    o ^= (o >> 3) & 0x70;
    return (uint32_t)((d >> 6) * 16384) + o;
}

#define LO_OFF     32768           // 2*lo tile after hi tile (each 32KB)
#define SMEM_TOTAL 65536

__device__ __forceinline__ void ldsm4t(uint32_t* r, uint32_t addr) {
    asm volatile("ldmatrix.sync.aligned.m8n8.x4.trans.shared.b16 {%0,%1,%2,%3}, [%4];"
                 : "=r"(r[0]), "=r"(r[1]), "=r"(r[2]), "=r"(r[3]) : "r"(addr));
}

__device__ __forceinline__ void mma_bf16(float* d, const uint32_t* a,
                                         uint32_t b0, uint32_t b1) {
    asm volatile(
        "mma.sync.aligned.m16n8k16.row.col.f32.bf16.bf16.f32 "
        "{%0,%1,%2,%3}, {%4,%5,%6,%7}, {%8,%9}, {%0,%1,%2,%3};"
        : "+f"(d[0]), "+f"(d[1]), "+f"(d[2]), "+f"(d[3])
        : "r"(a[0]), "r"(a[1]), "r"(a[2]), "r"(a[3]), "r"(b0), "r"(b1));
}

// ---------------------------------------------------------------------------
// Kernel 1: convert(+diag) -> tensor-core P = H^T H + H^T(2L) -> STG partial.
// No atomics for the matrix: each block owns a private 64KB partial slice.
// Warp w owns rows [(w&7)*16, +16) x cols [(w>>3)*64, +64).
// ---------------------------------------------------------------------------
__global__ __launch_bounds__(NTHREADS, 1)
void gram_diag(const float* __restrict__ X, const float* __restrict__ Y) {
    extern __shared__ char smem[];
    const uint32_t sb = smem_u32(smem);
    const int tid  = threadIdx.x;
    const int w    = tid >> 5;
    const int lane = tid & 31;

    const bool isX  = blockIdx.x < (NBLOCKS / 2);
    const int chunk = isX ? blockIdx.x : blockIdx.x - NBLOCKS / 2;
    const float* base  = (isX ? X : Y) + (size_t)chunk * CHUNK * DIM;
    const float* ybase = Y + (size_t)chunk * CHUNK * DIM;   // diag (X blocks)

    // ldmatrix per-lane tile-row selectors
    const int lr    = lane & 7;
    const int a_kad = (lane & 16) ? 8 : 0;
    const int a_mad = (lane & 8)  ? 8 : 0;
    const int b_kad = (lane & 8)  ? 8 : 0;
    const int b_nad = (lane & 16) ? 8 : 0;
    const int m0    = (w & 7) * 16;        // warp's output row slab
    const int nbase = (w >> 3) * 64;       // warp's output column half

    // ---- convert fp32 -> bf16 hi and 2*lo tiles; X blocks also do diag ----
    float s2 = 0.0f, s3 = 0.0f;
    #pragma unroll
    for (int it = 0; it < 8; ++it) {
        const int r = w + 16 * it;                    // sample row
        const float4 v = *reinterpret_cast<const float4*>(base + r * DIM + lane * 4);
        __nv_bfloat162 h01 = __floats2bfloat162_rn(v.x, v.y);
        __nv_bfloat162 h23 = __floats2bfloat162_rn(v.z, v.w);
        __nv_bfloat162 l01 = __floats2bfloat162_rn(2.0f * (v.x - __bfloat162float(h01.x)),
                                                   2.0f * (v.y - __bfloat162float(h01.y)));
        __nv_bfloat162 l23 = __floats2bfloat162_rn(2.0f * (v.z - __bfloat162float(h23.x)),
                                                   2.0f * (v.w - __bfloat162float(h23.y)));
        const uint32_t o = toff(r, lane * 4);
        uint2 hv, lv;
        hv.x = *reinterpret_cast<uint32_t*>(&h01);
        hv.y = *reinterpret_cast<uint32_t*>(&h23);
        lv.x = *reinterpret_cast<uint32_t*>(&l01);
        lv.y = *reinterpret_cast<uint32_t*>(&l23);
        *reinterpret_cast<uint2*>(smem + o)          = hv;
        *reinterpret_cast<uint2*>(smem + LO_OFF + o) = lv;

        if (isX) {                                    // diag: d_r = <x_r, y_r>
            const float4 u = *reinterpret_cast<const float4*>(ybase + r * DIM + lane * 4);
            float d = v.x * u.x + v.y * u.y + v.z * u.z + v.w * u.w;
            #pragma unroll
            for (int o2 = 16; o2; o2 >>= 1) d += __shfl_xor_sync(0xffffffffu, d, o2);
            s3 += d;
            s2 += d * d;
        }
    }
    if (isX && lane == 0) {
        atomicAdd(&g_S3, s3);
        atomicAdd(&g_S2, s2);
    }
    __syncthreads();

    // ---- MMA mainloop: P = H^T H + H^T(2L); A-frags hi only ----
    float acc[8][4];
    #pragma unroll
    for (int nt = 0; nt < 8; ++nt)
        #pragma unroll
        for (int i = 0; i < 4; ++i) acc[nt][i] = 0.0f;

    for (int ks = 0; ks < 8; ++ks) {
        const int k0 = ks * 16;
        uint32_t ahi[4];
        ldsm4t(ahi, sb + toff(k0 + lr + a_kad, m0 + a_mad));

        #pragma unroll
        for (int ntp = 0; ntp < 4; ++ntp) {
            const int n0 = nbase + ntp * 16;
            uint32_t bhi[4], blo[4];
            const uint32_t boff = toff(k0 + lr + b_kad, n0 + b_nad);
            ldsm4t(bhi, sb + boff);
            ldsm4t(blo, sb + LO_OFF + boff);
            mma_bf16(acc[2 * ntp],     ahi, bhi[0], bhi[1]);
            mma_bf16(acc[2 * ntp],     ahi, blo[0], blo[1]);
            mma_bf16(acc[2 * ntp + 1], ahi, bhi[2], bhi[3]);
            mma_bf16(acc[2 * ntp + 1], ahi, blo[2], blo[3]);
        }
    }

    // ---- store partial P with plain STG.64 (private slice; no atomics) ----
    float* P = g_part[isX ? 0 : 1][chunk];
    const int row0 = m0 + (lane >> 2);
    const int col0 = (lane & 3) * 2;
    #pragma unroll
    for (int nt = 0; nt < 8; ++nt) {
        const int cc = nbase + nt * 8 + col0;
        *reinterpret_cast<float2*>(&P[row0 * DIM + cc]) =
            make_float2(acc[nt][0], acc[nt][1]);
        *reinterpret_cast<float2*>(&P[(row0 + 8) * DIM + cc]) =
            make_float2(acc[nt][2], acc[nt][3]);
    }
}

// ---------------------------------------------------------------------------
// Kernel 2: 64 blocks x 256. Element e: sx = sum_i Px_i[e], sy = sum_i Py_i[e],
// s1 += sx*sy. Coalesced reads (lane -> consecutive e). Ticket-last combines.
// No scratch re-zero needed: partials are fully overwritten each launch.
// ---------------------------------------------------------------------------
__global__ __launch_bounds__(256, 1)
void finalize(float* __restrict__ out) {
    __shared__ float    wsum[8];
    __shared__ unsigned s_last;
    const int tid  = threadIdx.x;
    const int lane = tid & 31;
    const int w    = tid >> 5;
    const int e    = blockIdx.x * 256 + tid;   // element index (16384 total)

    float sx = 0.0f, sy = 0.0f;
    #pragma unroll 8
    for (int i = 0; i < NPART; ++i) {
        sx += g_part[0][i][e];
        sy += g_part[1][i][e];
    }
    float s1 = sx * sy;

    #pragma unroll
    for (int o = 16; o; o >>= 1) s1 += __shfl_xor_sync(0xffffffffu, s1, o);
    if (lane == 0) wsum[w] = s1;
    __syncthreads();

    if (tid == 0) {
        float t = 0.0f;
        #pragma unroll
        for (int k = 0; k < 8; ++k) t += wsum[k];
        atomicAdd(&g_S1, t);
        __threadfence();
        s_last = atomicAdd(&g_ticket, 1u);
        if (s_last == FIN_BLOCKS - 1) {
            const float S1 = atomicAdd(&g_S1, 0.0f);   // coherent read
            const double loss =
                ((double)S1 - (double)g_S2) / ((double)NROWS * (double)(NROWS - 1))
                - 2.0 * (double)g_S3 / (double)NROWS;
            out[0] = (float)loss;
            g_S1 = 0.0f; g_S2 = 0.0f; g_S3 = 0.0f; g_ticket = 0u;
        }
    }
}

// ---------------------------------------------------------------------------
extern "C" void kernel_launch(void* const* d_in, const int* in_sizes, int n_in,
                              void* d_out, int out_size) {
    const float* X = (const float*)d_in[0];
    const float* Y = (const float*)d_in[1];
    float* out = (float*)d_out;

    static bool attr_set = false;   // idempotent host-side attribute
    if (!attr_set) {
        cudaFuncSetAttribute(gram_diag,
                             cudaFuncAttributeMaxDynamicSharedMemorySize, SMEM_TOTAL);
        attr_set = true;
    }

    gram_diag<<<NBLOCKS, NTHREADS, SMEM_TOTAL>>>(X, Y);
    finalize<<<FIN_BLOCKS, 256>>>(out);
}

// round 14
// speedup vs baseline: 1.1233x; 1.1233x over previous
#include <cuda_runtime.h>
#include <cuda_bf16.h>
#include <cstdint>

#define NROWS 8192
#define DIM   128
#define CHUNK 128                  // samples per tile
#define NBLOCKS 128                // b<64: X chunk b (+diag); b>=64: Y chunk b-64
#define NTHREADS 512               // 16 warps
#define NPART 64                   // partials per matrix
#define NELEM4 4096                // DIM*DIM/4 float4 elements per partial
#define FIN_BLOCKS 16

// ---------------- device-global scratch (no allocations allowed) -----------
// g_part[m][i] = block i's raw partial of P_m = H^T H + 2 H^T L (8 MB total).
// Fully overwritten every launch -> no zeroing pass needed.
__device__ float    g_part[2][NPART][DIM * DIM];
__device__ float    g_S1;               // <Px,Py>_F accumulator
__device__ float    g_S2;               // sum d_i^2
__device__ float    g_S3;               // sum d_i
__device__ unsigned g_ticket;

// ---------------- helpers ---------------------------------------------------
__device__ __forceinline__ uint32_t smem_u32(const void* p) {
    uint32_t a;
    asm("{ .reg .u64 t; cvta.to.shared.u64 t, %1; cvt.u32.u64 %0, t; }" : "=r"(a) : "l"(p));
    return a;
}

// Tile stored SAMPLE-major: S[k][d]; two 16KB subtiles by d>>6; SW128 swizzle.
__device__ __forceinline__ uint32_t toff(int k, int d) {
    uint32_t o = (uint32_t)(k * 128 + (d & 63) * 2);
    o ^= (o >> 3) & 0x70;
    return (uint32_t)((d >> 6) * 16384) + o;
}

#define LO_OFF     32768           // 2*lo tile after hi tile (each 32KB)
#define SMEM_TOTAL 65536

__device__ __forceinline__ void ldsm4t(uint32_t* r, uint32_t addr) {
    asm volatile("ldmatrix.sync.aligned.m8n8.x4.trans.shared.b16 {%0,%1,%2,%3}, [%4];"
                 : "=r"(r[0]), "=r"(r[1]), "=r"(r[2]), "=r"(r[3]) : "r"(addr));
}

__device__ __forceinline__ void mma_bf16(float* d, const uint32_t* a,
                                         uint32_t b0, uint32_t b1) {
    asm volatile(
        "mma.sync.aligned.m16n8k16.row.col.f32.bf16.bf16.f32 "
        "{%0,%1,%2,%3}, {%4,%5,%6,%7}, {%8,%9}, {%0,%1,%2,%3};"
        : "+f"(d[0]), "+f"(d[1]), "+f"(d[2]), "+f"(d[3])
        : "r"(a[0]), "r"(a[1]), "r"(a[2]), "r"(a[3]), "r"(b0), "r"(b1));
}

// ---------------------------------------------------------------------------
// Kernel 1: convert(+diag) -> tensor-core P = H^T H + H^T(2L) -> STG partial.
// (Unchanged from R13: measured ~8.3us.)
// ---------------------------------------------------------------------------
__global__ __launch_bounds__(NTHREADS, 1)
void gram_diag(const float* __restrict__ X, const float* __restrict__ Y) {
    extern __shared__ char smem[];
    const uint32_t sb = smem_u32(smem);
    const int tid  = threadIdx.x;
    const int w    = tid >> 5;
    const int lane = tid & 31;

    const bool isX  = blockIdx.x < (NBLOCKS / 2);
    const int chunk = isX ? blockIdx.x : blockIdx.x - NBLOCKS / 2;
    const float* base  = (isX ? X : Y) + (size_t)chunk * CHUNK * DIM;
    const float* ybase = Y + (size_t)chunk * CHUNK * DIM;   // diag (X blocks)

    // ldmatrix per-lane tile-row selectors
    const int lr    = lane & 7;
    const int a_kad = (lane & 16) ? 8 : 0;
    const int a_mad = (lane & 8)  ? 8 : 0;
    const int b_kad = (lane & 8)  ? 8 : 0;
    const int b_nad = (lane & 16) ? 8 : 0;
    const int m0    = (w & 7) * 16;        // warp's output row slab
    const int nbase = (w >> 3) * 64;       // warp's output column half

    // ---- convert fp32 -> bf16 hi and 2*lo tiles; X blocks also do diag ----
    float s2 = 0.0f, s3 = 0.0f;
    #pragma unroll
    for (int it = 0; it < 8; ++it) {
        const int r = w + 16 * it;                    // sample row
        const float4 v = *reinterpret_cast<const float4*>(base + r * DIM + lane * 4);
        __nv_bfloat162 h01 = __floats2bfloat162_rn(v.x, v.y);
        __nv_bfloat162 h23 = __floats2bfloat162_rn(v.z, v.w);
        __nv_bfloat162 l01 = __floats2bfloat162_rn(2.0f * (v.x - __bfloat162float(h01.x)),
                                                   2.0f * (v.y - __bfloat162float(h01.y)));
        __nv_bfloat162 l23 = __floats2bfloat162_rn(2.0f * (v.z - __bfloat162float(h23.x)),
                                                   2.0f * (v.w - __bfloat162float(h23.y)));
        const uint32_t o = toff(r, lane * 4);
        uint2 hv, lv;
        hv.x = *reinterpret_cast<uint32_t*>(&h01);
        hv.y = *reinterpret_cast<uint32_t*>(&h23);
        lv.x = *reinterpret_cast<uint32_t*>(&l01);
        lv.y = *reinterpret_cast<uint32_t*>(&l23);
        *reinterpret_cast<uint2*>(smem + o)          = hv;
        *reinterpret_cast<uint2*>(smem + LO_OFF + o) = lv;

        if (isX) {                                    // diag: d_r = <x_r, y_r>
            const float4 u = *reinterpret_cast<const float4*>(ybase + r * DIM + lane * 4);
            float d = v.x * u.x + v.y * u.y + v.z * u.z + v.w * u.w;
            #pragma unroll
            for (int o2 = 16; o2; o2 >>= 1) d += __shfl_xor_sync(0xffffffffu, d, o2);
            s3 += d;
            s2 += d * d;
        }
    }
    if (isX && lane == 0) {
        atomicAdd(&g_S3, s3);
        atomicAdd(&g_S2, s2);
    }
    __syncthreads();

    // ---- MMA mainloop: P = H^T H + H^T(2L); A-frags hi only ----
    float acc[8][4];
    #pragma unroll
    for (int nt = 0; nt < 8; ++nt)
        #pragma unroll
        for (int i = 0; i < 4; ++i) acc[nt][i] = 0.0f;

    for (int ks = 0; ks < 8; ++ks) {
        const int k0 = ks * 16;
        uint32_t ahi[4];
        ldsm4t(ahi, sb + toff(k0 + lr + a_kad, m0 + a_mad));

        #pragma unroll
        for (int ntp = 0; ntp < 4; ++ntp) {
            const int n0 = nbase + ntp * 16;
            uint32_t bhi[4], blo[4];
            const uint32_t boff = toff(k0 + lr + b_kad, n0 + b_nad);
            ldsm4t(bhi, sb + boff);
            ldsm4t(blo, sb + LO_OFF + boff);
            mma_bf16(acc[2 * ntp],     ahi, bhi[0], bhi[1]);
            mma_bf16(acc[2 * ntp],     ahi, blo[0], blo[1]);
            mma_bf16(acc[2 * ntp + 1], ahi, bhi[2], bhi[3]);
            mma_bf16(acc[2 * ntp + 1], ahi, blo[2], blo[3]);
        }
    }

    // ---- store partial P with plain STG.64 (private slice; no atomics) ----
    float* P = g_part[isX ? 0 : 1][chunk];
    const int row0 = m0 + (lane >> 2);
    const int col0 = (lane & 3) * 2;
    #pragma unroll
    for (int nt = 0; nt < 8; ++nt) {
        const int cc = nbase + nt * 8 + col0;
        *reinterpret_cast<float2*>(&P[row0 * DIM + cc]) =
            make_float2(acc[nt][0], acc[nt][1]);
        *reinterpret_cast<float2*>(&P[(row0 + 8) * DIM + cc]) =
            make_float2(acc[nt][2], acc[nt][3]);
    }
}

// ---------------------------------------------------------------------------
// Kernel 2: 16 blocks x 1024. Thread (e4, g): sum 16 partials (float4) of
// both matrices -> smem -> combine 4 groups -> dot -> reduce -> ticket.
// 32 independent 16B loads/thread = 8MB in flight chip-wide (covers L2 lat).
// ---------------------------------------------------------------------------
__global__ __launch_bounds__(1024, 1)
void finalize(float* __restrict__ out) {
    __shared__ float4   sxs[4][256];
    __shared__ float4   sys[4][256];
    __shared__ float    wsum[8];
    const int tid = threadIdx.x;
    const int el  = tid & 255;              // element slot within block
    const int g   = tid >> 8;               // partial group (0..3)
    const int e4  = blockIdx.x * 256 + el;  // global float4 index

    const float4* Px = reinterpret_cast<const float4*>(g_part[0]) + (size_t)g * 16 * NELEM4 + e4;
    const float4* Py = reinterpret_cast<const float4*>(g_part[1]) + (size_t)g * 16 * NELEM4 + e4;

    float4 sx = make_float4(0.f, 0.f, 0.f, 0.f);
    float4 sy = make_float4(0.f, 0.f, 0.f, 0.f);
    #pragma unroll
    for (int i = 0; i < 16; ++i) {
        const float4 a = Px[(size_t)i * NELEM4];
        const float4 b = Py[(size_t)i * NELEM4];
        sx.x += a.x; sx.y += a.y; sx.z += a.z; sx.w += a.w;
        sy.x += b.x; sy.y += b.y; sy.z += b.z; sy.w += b.w;
    }
    sxs[g][el] = sx;
    sys[g][el] = sy;
    __syncthreads();

    if (g == 0) {
        const float4 x1 = sxs[1][el], x2 = sxs[2][el], x3 = sxs[3][el];
        const float4 y1 = sys[1][el], y2 = sys[2][el], y3 = sys[3][el];
        const float ax = sx.x + x1.x + x2.x + x3.x;
        const float ay = sx.y + x1.y + x2.y + x3.y;
        const float az = sx.z + x1.z + x2.z + x3.z;
        const float aw = sx.w + x1.w + x2.w + x3.w;
        const float bx = sy.x + y1.x + y2.x + y3.x;
        const float by = sy.y + y1.y + y2.y + y3.y;
        const float bz = sy.z + y1.z + y2.z + y3.z;
        const float bw = sy.w + y1.w + y2.w + y3.w;
        float s1 = ax * bx + ay * by + az * bz + aw * bw;

        const int lane = tid & 31;
        #pragma unroll
        for (int o = 16; o; o >>= 1) s1 += __shfl_xor_sync(0xffffffffu, s1, o);
        if (lane == 0) wsum[tid >> 5] = s1;
    }
    __syncthreads();

    if (tid == 0) {
        float t = 0.0f;
        #pragma unroll
        for (int k = 0; k < 8; ++k) t += wsum[k];
        atomicAdd(&g_S1, t);
        __threadfence();
        const unsigned last = atomicAdd(&g_ticket, 1u);
        if (last == FIN_BLOCKS - 1) {
            const float S1 = atomicAdd(&g_S1, 0.0f);   // coherent read
            const double loss =
                ((double)S1 - (double)g_S2) / ((double)NROWS * (double)(NROWS - 1))
                - 2.0 * (double)g_S3 / (double)NROWS;
            out[0] = (float)loss;
            g_S1 = 0.0f; g_S2 = 0.0f; g_S3 = 0.0f; g_ticket = 0u;
        }
    }
}

// ---------------------------------------------------------------------------
extern "C" void kernel_launch(void* const* d_in, const int* in_sizes, int n_in,
                              void* d_out, int out_size) {
    const float* X = (const float*)d_in[0];
    const float* Y = (const float*)d_in[1];
    float* out = (float*)d_out;

    static bool attr_set = false;   // idempotent host-side attribute
    if (!attr_set) {
        cudaFuncSetAttribute(gram_diag,
                             cudaFuncAttributeMaxDynamicSharedMemorySize, SMEM_TOTAL);
        attr_set = true;
    }

    gram_diag<<<NBLOCKS, NTHREADS, SMEM_TOTAL>>>(X, Y);
    finalize<<<FIN_BLOCKS, 1024>>>(out);
}